// round 2
// baseline (speedup 1.0000x reference)
#include <cuda_runtime.h>

#define B_   8
#define S_   1024
#define HID_ 1024
#define NH_  16
#define HD_  64

// ---------------- scratch (no allocations allowed) ----------------
__device__ float g_q[B_ * NH_ * S_ * HD_];            // 32 MB, [b,h,s,d], pre-scaled by 1/8
__device__ float g_k[B_ * NH_ * S_ * HD_];            // 32 MB
__device__ float g_v[B_ * NH_ * S_ * HD_];            // 32 MB
__device__ float g_scores[B_ * NH_ * S_ * S_];        // 512 MB, [b,h,q,k]
__device__ float g_ctx[B_ * S_ * HID_];               // 32 MB, [b,s,h,d] == [b,s,hid]
__device__ float g_h[B_ * S_ * HID_];                 // 32 MB, pre-LN activations

// =================================================================
// K1: QKV projection.  C[m,n] = X[m,:] . W[n,:],  M=8192, N=3072, K=1024
// Epilogue: +q_bias (*0.125) for q, +v_bias for v; scatter into head layout.
// =================================================================
__global__ void __launch_bounds__(256) qkv_gemm_kernel(
    const float* __restrict__ X, const float* __restrict__ W,
    const float* __restrict__ q_bias, const float* __restrict__ v_bias)
{
    __shared__ float As[8][128];
    __shared__ float Bs[8][128];
    const int K  = HID_;
    const int bm = blockIdx.y * 128;
    const int bn = blockIdx.x * 128;
    const int tid = threadIdx.x;
    const int tx = tid & 15;
    const int ty = tid >> 4;
    const int lr = tid >> 1;
    const int lc = (tid & 1) * 4;

    float acc[8][8];
#pragma unroll
    for (int i = 0; i < 8; i++)
#pragma unroll
        for (int j = 0; j < 8; j++) acc[i][j] = 0.f;

    const float* Aptr = X + (size_t)(bm + lr) * K + lc;
    const float* Bptr = W + (size_t)(bn + lr) * K + lc;

    for (int k0 = 0; k0 < K; k0 += 8) {
        float4 a = *(const float4*)(Aptr + k0);
        float4 b = *(const float4*)(Bptr + k0);
        As[lc + 0][lr] = a.x; As[lc + 1][lr] = a.y;
        As[lc + 2][lr] = a.z; As[lc + 3][lr] = a.w;
        Bs[lc + 0][lr] = b.x; Bs[lc + 1][lr] = b.y;
        Bs[lc + 2][lr] = b.z; Bs[lc + 3][lr] = b.w;
        __syncthreads();
#pragma unroll
        for (int kk = 0; kk < 8; kk++) {
            float ra[8], rb[8];
#pragma unroll
            for (int i = 0; i < 8; i++) ra[i] = As[kk][ty * 8 + i];
#pragma unroll
            for (int j = 0; j < 8; j++) rb[j] = Bs[kk][tx * 8 + j];
#pragma unroll
            for (int i = 0; i < 8; i++)
#pragma unroll
                for (int j = 0; j < 8; j++)
                    acc[i][j] = fmaf(ra[i], rb[j], acc[i][j]);
        }
        __syncthreads();
    }

#pragma unroll
    for (int i = 0; i < 8; i++) {
        int m  = bm + ty * 8 + i;
        int bb = m >> 10;
        int ss = m & 1023;
#pragma unroll
        for (int j = 0; j < 8; j++) {
            int n   = bn + tx * 8 + j;
            float v = acc[i][j];
            if (n < HID_) {
                v = (v + q_bias[n]) * 0.125f;          // 1/sqrt(HD)
                int h = n >> 6, d = n & 63;
                g_q[(((size_t)(bb * NH_ + h)) * S_ + ss) * HD_ + d] = v;
            } else if (n < 2 * HID_) {
                int nn = n - HID_;
                int h = nn >> 6, d = nn & 63;
                g_k[(((size_t)(bb * NH_ + h)) * S_ + ss) * HD_ + d] = v;
            } else {
                int nn = n - 2 * HID_;
                v += v_bias[nn];
                int h = nn >> 6, d = nn & 63;
                g_v[(((size_t)(bb * NH_ + h)) * S_ + ss) * HD_ + d] = v;
            }
        }
    }
}

// =================================================================
// K2: batched scores.  S[q,k] = qh[q,:] . kh[k,:]  (+rel_pos +rel_2d, mask)
// per (b,h): M=N=1024, K=64
// =================================================================
__global__ void __launch_bounds__(256) scores_kernel(
    const float* __restrict__ rel_pos, const float* __restrict__ rel2d,
    const unsigned char* __restrict__ mask)
{
    __shared__ float As[8][128];
    __shared__ float Bs[8][128];
    const int bz = blockIdx.z;             // b*NH + h
    const int bm = blockIdx.y * 128;
    const int bn = blockIdx.x * 128;
    const int tid = threadIdx.x;
    const int tx = tid & 15, ty = tid >> 4;
    const int lr = tid >> 1,  lc = (tid & 1) * 4;

    const float* Q  = g_q + (size_t)bz * S_ * HD_;
    const float* Kp = g_k + (size_t)bz * S_ * HD_;

    float acc[8][8];
#pragma unroll
    for (int i = 0; i < 8; i++)
#pragma unroll
        for (int j = 0; j < 8; j++) acc[i][j] = 0.f;

    for (int k0 = 0; k0 < HD_; k0 += 8) {
        float4 a = *(const float4*)(Q  + (size_t)(bm + lr) * HD_ + k0 + lc);
        float4 b = *(const float4*)(Kp + (size_t)(bn + lr) * HD_ + k0 + lc);
        As[lc + 0][lr] = a.x; As[lc + 1][lr] = a.y;
        As[lc + 2][lr] = a.z; As[lc + 3][lr] = a.w;
        Bs[lc + 0][lr] = b.x; Bs[lc + 1][lr] = b.y;
        Bs[lc + 2][lr] = b.z; Bs[lc + 3][lr] = b.w;
        __syncthreads();
#pragma unroll
        for (int kk = 0; kk < 8; kk++) {
            float ra[8], rb[8];
#pragma unroll
            for (int i = 0; i < 8; i++) ra[i] = As[kk][ty * 8 + i];
#pragma unroll
            for (int j = 0; j < 8; j++) rb[j] = Bs[kk][tx * 8 + j];
#pragma unroll
            for (int i = 0; i < 8; i++)
#pragma unroll
                for (int j = 0; j < 8; j++)
                    acc[i][j] = fmaf(ra[i], rb[j], acc[i][j]);
        }
        __syncthreads();
    }

    const int h  = bz & 15;
    const int bb = bz >> 4;
    float* out = g_scores + (size_t)bz * S_ * S_;
#pragma unroll
    for (int i = 0; i < 8; i++) {
        int m = bm + ty * 8 + i;
        const float* rp = rel_pos + ((size_t)h * S_ + m) * S_;
        const float* r2 = rel2d   + ((size_t)h * S_ + m) * S_;
#pragma unroll
        for (int j = 0; j < 8; j++) {
            int n   = bn + tx * 8 + j;
            float v = acc[i][j] + rp[n] + r2[n];
            if (mask[bb * S_ + n]) v = -1e30f;
            out[(size_t)m * S_ + n] = v;
        }
    }
}

// =================================================================
// K3: row softmax over g_scores (in place). One block (128 thr) per row.
// =================================================================
__global__ void __launch_bounds__(128) softmax_kernel()
{
    const size_t row = blockIdx.x;
    float* p = g_scores + row * S_;
    const int tid = threadIdx.x;

    float4 v0 = *(const float4*)(p + tid * 4);
    float4 v1 = *(const float4*)(p + 512 + tid * 4);

    __shared__ float red[128];
    float m = fmaxf(fmaxf(fmaxf(v0.x, v0.y), fmaxf(v0.z, v0.w)),
                    fmaxf(fmaxf(v1.x, v1.y), fmaxf(v1.z, v1.w)));
    red[tid] = m; __syncthreads();
    for (int s = 64; s > 0; s >>= 1) {
        if (tid < s) red[tid] = fmaxf(red[tid], red[tid + s]);
        __syncthreads();
    }
    m = red[0];
    __syncthreads();

    v0.x = expf(v0.x - m); v0.y = expf(v0.y - m);
    v0.z = expf(v0.z - m); v0.w = expf(v0.w - m);
    v1.x = expf(v1.x - m); v1.y = expf(v1.y - m);
    v1.z = expf(v1.z - m); v1.w = expf(v1.w - m);

    float s8 = v0.x + v0.y + v0.z + v0.w + v1.x + v1.y + v1.z + v1.w;
    red[tid] = s8; __syncthreads();
    for (int s = 64; s > 0; s >>= 1) {
        if (tid < s) red[tid] += red[tid + s];
        __syncthreads();
    }
    float inv = 1.0f / red[0];

    v0.x *= inv; v0.y *= inv; v0.z *= inv; v0.w *= inv;
    v1.x *= inv; v1.y *= inv; v1.z *= inv; v1.w *= inv;
    *(float4*)(p + tid * 4)       = v0;
    *(float4*)(p + 512 + tid * 4) = v1;
}

// =================================================================
// K4: batched ctx = P @ V.  per (b,h): M=1024, N=64, K=1024.
// Output scattered to [b, s, h, d] (== contiguous [b,s,hid]).
// =================================================================
__global__ void __launch_bounds__(256) ctx_kernel()
{
    __shared__ float As[8][128];
    __shared__ float Bs[8][64];
    const int bz = blockIdx.z;
    const int bm = blockIdx.y * 128;
    const int tid = threadIdx.x;
    const int tx = tid & 15, ty = tid >> 4;   // TM=8 x TN=4
    const int lr = tid >> 1,  lc = (tid & 1) * 4;

    const float* P = g_scores + (size_t)bz * S_ * S_;
    const float* V = g_v      + (size_t)bz * S_ * HD_;

    float acc[8][4];
#pragma unroll
    for (int i = 0; i < 8; i++)
#pragma unroll
        for (int j = 0; j < 4; j++) acc[i][j] = 0.f;

    for (int k0 = 0; k0 < S_; k0 += 8) {
        float4 a = *(const float4*)(P + (size_t)(bm + lr) * S_ + k0 + lc);
        As[lc + 0][lr] = a.x; As[lc + 1][lr] = a.y;
        As[lc + 2][lr] = a.z; As[lc + 3][lr] = a.w;
        int i0 = tid, i1 = tid + 256;
        Bs[i0 >> 6][i0 & 63] = V[(size_t)(k0 + (i0 >> 6)) * HD_ + (i0 & 63)];
        Bs[i1 >> 6][i1 & 63] = V[(size_t)(k0 + (i1 >> 6)) * HD_ + (i1 & 63)];
        __syncthreads();
#pragma unroll
        for (int kk = 0; kk < 8; kk++) {
            float ra[8], rb[4];
#pragma unroll
            for (int i = 0; i < 8; i++) ra[i] = As[kk][ty * 8 + i];
#pragma unroll
            for (int j = 0; j < 4; j++) rb[j] = Bs[kk][tx * 4 + j];
#pragma unroll
            for (int i = 0; i < 8; i++)
#pragma unroll
                for (int j = 0; j < 4; j++)
                    acc[i][j] = fmaf(ra[i], rb[j], acc[i][j]);
        }
        __syncthreads();
    }

    const int bb = bz >> 4, h = bz & 15;
#pragma unroll
    for (int i = 0; i < 8; i++) {
        int q = bm + ty * 8 + i;
#pragma unroll
        for (int j = 0; j < 4; j++) {
            int d = tx * 4 + j;
            g_ctx[(((size_t)bb * S_ + q) * NH_ + h) * HD_ + d] = acc[i][j];
        }
    }
}

// =================================================================
// K5a: out projection. h = ctx @ w_out^T + b_out + x.  M=8192,N=1024,K=1024
// =================================================================
__global__ void __launch_bounds__(256) outproj_kernel(
    const float* __restrict__ Wout, const float* __restrict__ b_out,
    const float* __restrict__ X)
{
    __shared__ float As[8][128];
    __shared__ float Bs[8][128];
    const int K  = HID_;
    const int bm = blockIdx.y * 128;
    const int bn = blockIdx.x * 128;
    const int tid = threadIdx.x;
    const int tx = tid & 15, ty = tid >> 4;
    const int lr = tid >> 1,  lc = (tid & 1) * 4;

    float acc[8][8];
#pragma unroll
    for (int i = 0; i < 8; i++)
#pragma unroll
        for (int j = 0; j < 8; j++) acc[i][j] = 0.f;

    const float* Aptr = g_ctx + (size_t)(bm + lr) * K + lc;
    const float* Bptr = Wout  + (size_t)(bn + lr) * K + lc;

    for (int k0 = 0; k0 < K; k0 += 8) {
        float4 a = *(const float4*)(Aptr + k0);
        float4 b = *(const float4*)(Bptr + k0);
        As[lc + 0][lr] = a.x; As[lc + 1][lr] = a.y;
        As[lc + 2][lr] = a.z; As[lc + 3][lr] = a.w;
        Bs[lc + 0][lr] = b.x; Bs[lc + 1][lr] = b.y;
        Bs[lc + 2][lr] = b.z; Bs[lc + 3][lr] = b.w;
        __syncthreads();
#pragma unroll
        for (int kk = 0; kk < 8; kk++) {
            float ra[8], rb[8];
#pragma unroll
            for (int i = 0; i < 8; i++) ra[i] = As[kk][ty * 8 + i];
#pragma unroll
            for (int j = 0; j < 8; j++) rb[j] = Bs[kk][tx * 8 + j];
#pragma unroll
            for (int i = 0; i < 8; i++)
#pragma unroll
                for (int j = 0; j < 8; j++)
                    acc[i][j] = fmaf(ra[i], rb[j], acc[i][j]);
        }
        __syncthreads();
    }

#pragma unroll
    for (int i = 0; i < 8; i++) {
        int m = bm + ty * 8 + i;
#pragma unroll
        for (int j = 0; j < 8; j++) {
            int n = bn + tx * 8 + j;
            g_h[(size_t)m * HID_ + n] =
                acc[i][j] + b_out[n] + X[(size_t)m * HID_ + n];
        }
    }
}

// =================================================================
// K5b: LayerNorm per row of g_h -> d_out
// =================================================================
__global__ void __launch_bounds__(256) layernorm_kernel(
    const float* __restrict__ gamma, const float* __restrict__ beta,
    float* __restrict__ out)
{
    const size_t row = blockIdx.x;
    const float* hp = g_h + row * HID_;
    const int tid = threadIdx.x;
    const int n = tid * 4;

    float4 v = *(const float4*)(hp + n);
    __shared__ float red[256];

    red[tid] = v.x + v.y + v.z + v.w;
    __syncthreads();
    for (int s = 128; s > 0; s >>= 1) {
        if (tid < s) red[tid] += red[tid + s];
        __syncthreads();
    }
    float mean = red[0] * (1.0f / HID_);
    __syncthreads();

    float dx = v.x - mean, dy = v.y - mean, dz = v.z - mean, dw = v.w - mean;
    red[tid] = dx * dx + dy * dy + dz * dz + dw * dw;
    __syncthreads();
    for (int s = 128; s > 0; s >>= 1) {
        if (tid < s) red[tid] += red[tid + s];
        __syncthreads();
    }
    float inv = rsqrtf(red[0] * (1.0f / HID_) + 1e-12f);

    float4 o;
    o.x = dx * inv * gamma[n + 0] + beta[n + 0];
    o.y = dy * inv * gamma[n + 1] + beta[n + 1];
    o.z = dz * inv * gamma[n + 2] + beta[n + 2];
    o.w = dw * inv * gamma[n + 3] + beta[n + 3];
    *(float4*)(out + row * HID_ + n) = o;
}

// =================================================================
extern "C" void kernel_launch(void* const* d_in, const int* in_sizes, int n_in,
                              void* d_out, int out_size)
{
    const float*         x       = (const float*)d_in[0];
    const unsigned char* mask    = (const unsigned char*)d_in[1];
    const float*         rel_pos = (const float*)d_in[2];
    const float*         rel2d   = (const float*)d_in[3];
    const float*         w_qkv   = (const float*)d_in[4];
    const float*         q_bias  = (const float*)d_in[5];
    const float*         v_bias  = (const float*)d_in[6];
    const float*         w_out   = (const float*)d_in[7];
    const float*         b_out   = (const float*)d_in[8];
    const float*         gamma   = (const float*)d_in[9];
    const float*         beta    = (const float*)d_in[10];
    float*               out     = (float*)d_out;

    qkv_gemm_kernel<<<dim3(24, 64), 256>>>(x, w_qkv, q_bias, v_bias);
    scores_kernel<<<dim3(8, 8, B_ * NH_), 256>>>(rel_pos, rel2d, mask);
    softmax_kernel<<<dim3(B_ * NH_ * S_), 128>>>();
    ctx_kernel<<<dim3(1, 8, B_ * NH_), 256>>>();
    outproj_kernel<<<dim3(8, 64), 256>>>(w_out, b_out, x);
    layernorm_kernel<<<dim3(B_ * S_), 256>>>(gamma, beta, out);
}

// round 3
// speedup vs baseline: 2.7838x; 2.7838x over previous
#include <cuda_runtime.h>
#include <cstdint>

#define B_   8
#define S_   1024
#define HID_ 1024
#define NH_  16
#define HD_  64

// ---------------- scratch (no allocations allowed) ----------------
__device__ float g_q[B_ * NH_ * S_ * HD_];            // [b,h,s,d], pre-scaled by 1/8, +q_bias
__device__ float g_k[B_ * NH_ * S_ * HD_];
__device__ float g_v[B_ * NH_ * S_ * HD_];
__device__ float g_scores[(size_t)B_ * NH_ * S_ * S_];
__device__ float g_ctx[B_ * S_ * HID_];
__device__ float g_h[B_ * S_ * HID_];

// ---------------- helpers ----------------
__device__ __forceinline__ uint32_t smem_u32(const void* p) {
    return (uint32_t)__cvta_generic_to_shared(p);
}
__device__ __forceinline__ void cp16(uint32_t s, const void* g) {
    asm volatile("cp.async.cg.shared.global [%0], [%1], 16;\n" :: "r"(s), "l"(g));
}
__device__ __forceinline__ void cp_commit() { asm volatile("cp.async.commit_group;\n"); }
template<int N> __device__ __forceinline__ void cp_wait() {
    asm volatile("cp.async.wait_group %0;\n" :: "n"(N));
}
__device__ __forceinline__ void mma_tf32(float c[4],
    uint32_t a0, uint32_t a1, uint32_t a2, uint32_t a3, uint32_t b0, uint32_t b1)
{
    asm volatile(
        "mma.sync.aligned.m16n8k8.row.col.f32.tf32.tf32.f32 "
        "{%0,%1,%2,%3},{%4,%5,%6,%7},{%8,%9},{%0,%1,%2,%3};\n"
        : "+f"(c[0]), "+f"(c[1]), "+f"(c[2]), "+f"(c[3])
        : "r"(a0), "r"(a1), "r"(a2), "r"(a3), "r"(b0), "r"(b1));
}

// load 128 rows x 16 floats tile into smem [row*20 + col] via cp.async
__device__ __forceinline__ void cpa_tile128x16(float* dst, const float* src, int ld) {
    const int tid = threadIdx.x;
    const int row = tid >> 2;
    const int c4  = (tid & 3) * 4;
    cp16(smem_u32(dst + row * 20 + c4),        src + (size_t)row * ld + c4);
    cp16(smem_u32(dst + (row + 64) * 20 + c4), src + (size_t)(row + 64) * ld + c4);
}

// 128x128 block-tile compute on one BK=16 chunk (8 warps: 2m x 4n, warp tile 64x32)
__device__ __forceinline__ void mma_block_128x128(
    const float* As, const float* Bs,
    int warp_m, int warp_n, int gid, int tig, float acc[4][4][4])
{
#pragma unroll
    for (int ks = 0; ks < 16; ks += 8) {
        uint32_t a[4][4], b[4][2];
#pragma unroll
        for (int i = 0; i < 4; i++) {
            int r = warp_m * 64 + i * 16 + gid;
            a[i][0] = __float_as_uint(As[r * 20 + ks + tig]);
            a[i][1] = __float_as_uint(As[(r + 8) * 20 + ks + tig]);
            a[i][2] = __float_as_uint(As[r * 20 + ks + tig + 4]);
            a[i][3] = __float_as_uint(As[(r + 8) * 20 + ks + tig + 4]);
        }
#pragma unroll
        for (int j = 0; j < 4; j++) {
            int n = warp_n * 32 + j * 8 + gid;
            b[j][0] = __float_as_uint(Bs[n * 20 + ks + tig]);
            b[j][1] = __float_as_uint(Bs[n * 20 + ks + tig + 4]);
        }
#pragma unroll
        for (int i = 0; i < 4; i++)
#pragma unroll
            for (int j = 0; j < 4; j++)
                mma_tf32(acc[i][j], a[i][0], a[i][1], a[i][2], a[i][3], b[j][0], b[j][1]);
    }
}

// =================================================================
// K1: QKV projection. C[m,n] = X[m,:] . W[n,:], M=8192, N=3072, K=1024
// =================================================================
__device__ __forceinline__ void qkv_store(int bb, int ss, int n, float2 v,
                                          const float* qb, const float* vb)
{
    if (n < HID_) {
        float2 o;
        o.x = (v.x + qb[n]) * 0.125f;
        o.y = (v.y + qb[n + 1]) * 0.125f;
        int h = n >> 6, d = n & 63;
        *(float2*)&g_q[(((size_t)(bb * NH_ + h)) * S_ + ss) * HD_ + d] = o;
    } else if (n < 2 * HID_) {
        int nn = n - HID_;
        int h = nn >> 6, d = nn & 63;
        *(float2*)&g_k[(((size_t)(bb * NH_ + h)) * S_ + ss) * HD_ + d] = v;
    } else {
        int nn = n - 2 * HID_;
        float2 o;
        o.x = v.x + vb[nn];
        o.y = v.y + vb[nn + 1];
        int h = nn >> 6, d = nn & 63;
        *(float2*)&g_v[(((size_t)(bb * NH_ + h)) * S_ + ss) * HD_ + d] = o;
    }
}

__global__ void __launch_bounds__(256) qkv_gemm_kernel(
    const float* __restrict__ X, const float* __restrict__ W,
    const float* __restrict__ qb, const float* __restrict__ vb)
{
    __shared__ float As[2][128 * 20];
    __shared__ float Bs[2][128 * 20];
    const int bm = blockIdx.y * 128, bn = blockIdx.x * 128;
    const int tid = threadIdx.x, wid = tid >> 5, lane = tid & 31;
    const int gid = lane >> 2, tig = lane & 3;
    const int warp_m = wid >> 2, warp_n = wid & 3;

    float acc[4][4][4];
#pragma unroll
    for (int i = 0; i < 4; i++)
#pragma unroll
        for (int j = 0; j < 4; j++)
#pragma unroll
            for (int k = 0; k < 4; k++) acc[i][j][k] = 0.f;

    const float* Abase = X + (size_t)bm * HID_;
    const float* Bbase = W + (size_t)bn * HID_;

    cpa_tile128x16(As[0], Abase, HID_);
    cpa_tile128x16(Bs[0], Bbase, HID_);
    cp_commit();

    const int NC = HID_ / 16;
    for (int c = 0; c < NC; c++) {
        int cur = c & 1;
        if (c + 1 < NC) {
            cpa_tile128x16(As[cur ^ 1], Abase + (c + 1) * 16, HID_);
            cpa_tile128x16(Bs[cur ^ 1], Bbase + (c + 1) * 16, HID_);
            cp_commit();
            cp_wait<1>();
        } else {
            cp_wait<0>();
        }
        __syncthreads();
        mma_block_128x128(As[cur], Bs[cur], warp_m, warp_n, gid, tig, acc);
        __syncthreads();
    }

    const int bb = bm >> 10, ss0 = bm & 1023;
#pragma unroll
    for (int i = 0; i < 4; i++) {
        int r = warp_m * 64 + i * 16 + gid;
#pragma unroll
        for (int j = 0; j < 4; j++) {
            int n = bn + warp_n * 32 + j * 8 + tig * 2;
            qkv_store(bb, ss0 + r,     n, make_float2(acc[i][j][0], acc[i][j][1]), qb, vb);
            qkv_store(bb, ss0 + r + 8, n, make_float2(acc[i][j][2], acc[i][j][3]), qb, vb);
        }
    }
}

// =================================================================
// K2: scores = Q.K^T + rel_pos + rel_2d (+mask). per (b,h): 1024x1024, K=64
// grid z = h*8 + b so concurrent CTAs share rel-pos in L2
// =================================================================
__global__ void __launch_bounds__(256) scores_kernel(
    const float* __restrict__ rel_pos, const float* __restrict__ rel2d,
    const unsigned char* __restrict__ mask)
{
    __shared__ float As[2][128 * 20];
    __shared__ float Bs[2][128 * 20];
    const int z = blockIdx.z;
    const int h = z >> 3, bb = z & 7;
    const int bh = bb * NH_ + h;
    const int bm = blockIdx.y * 128, bn = blockIdx.x * 128;
    const int tid = threadIdx.x, wid = tid >> 5, lane = tid & 31;
    const int gid = lane >> 2, tig = lane & 3;
    const int warp_m = wid >> 2, warp_n = wid & 3;

    float acc[4][4][4];
#pragma unroll
    for (int i = 0; i < 4; i++)
#pragma unroll
        for (int j = 0; j < 4; j++)
#pragma unroll
            for (int k = 0; k < 4; k++) acc[i][j][k] = 0.f;

    const float* Abase = g_q + (size_t)bh * S_ * HD_ + (size_t)bm * HD_;
    const float* Bbase = g_k + (size_t)bh * S_ * HD_ + (size_t)bn * HD_;

    cpa_tile128x16(As[0], Abase, HD_);
    cpa_tile128x16(Bs[0], Bbase, HD_);
    cp_commit();

    const int NC = HD_ / 16;
    for (int c = 0; c < NC; c++) {
        int cur = c & 1;
        if (c + 1 < NC) {
            cpa_tile128x16(As[cur ^ 1], Abase + (c + 1) * 16, HD_);
            cpa_tile128x16(Bs[cur ^ 1], Bbase + (c + 1) * 16, HD_);
            cp_commit();
            cp_wait<1>();
        } else {
            cp_wait<0>();
        }
        __syncthreads();
        mma_block_128x128(As[cur], Bs[cur], warp_m, warp_n, gid, tig, acc);
        __syncthreads();
    }

    float* out = g_scores + (size_t)bh * S_ * S_;
    const unsigned char* mrow = mask + bb * S_;
#pragma unroll
    for (int i = 0; i < 4; i++) {
        int r0 = bm + warp_m * 64 + i * 16 + gid;
#pragma unroll
        for (int j = 0; j < 4; j++) {
            int n = bn + warp_n * 32 + j * 8 + tig * 2;
            float2 rp0 = *(const float2*)&rel_pos[((size_t)h * S_ + r0) * S_ + n];
            float2 r20 = *(const float2*)&rel2d[((size_t)h * S_ + r0) * S_ + n];
            float2 rp1 = *(const float2*)&rel_pos[((size_t)h * S_ + r0 + 8) * S_ + n];
            float2 r21 = *(const float2*)&rel2d[((size_t)h * S_ + r0 + 8) * S_ + n];
            float m0 = mrow[n] ? -1e30f : 0.f;
            float m1 = mrow[n + 1] ? -1e30f : 0.f;
            float2 v0, v1;
            v0.x = acc[i][j][0] + rp0.x + r20.x + m0;
            v0.y = acc[i][j][1] + rp0.y + r20.y + m1;
            v1.x = acc[i][j][2] + rp1.x + r21.x + m0;
            v1.y = acc[i][j][3] + rp1.y + r21.y + m1;
            *(float2*)&out[(size_t)r0 * S_ + n] = v0;
            *(float2*)&out[(size_t)(r0 + 8) * S_ + n] = v1;
        }
    }
}

// =================================================================
// K3: row softmax over g_scores (in place). One block (128 thr) per row.
// =================================================================
__global__ void __launch_bounds__(128) softmax_kernel()
{
    const size_t row = blockIdx.x;
    float* p = g_scores + row * S_;
    const int tid = threadIdx.x;

    float4 v0 = *(const float4*)(p + tid * 4);
    float4 v1 = *(const float4*)(p + 512 + tid * 4);

    __shared__ float red[128];
    float m = fmaxf(fmaxf(fmaxf(v0.x, v0.y), fmaxf(v0.z, v0.w)),
                    fmaxf(fmaxf(v1.x, v1.y), fmaxf(v1.z, v1.w)));
    red[tid] = m; __syncthreads();
    for (int s = 64; s > 0; s >>= 1) {
        if (tid < s) red[tid] = fmaxf(red[tid], red[tid + s]);
        __syncthreads();
    }
    m = red[0];
    __syncthreads();

    v0.x = expf(v0.x - m); v0.y = expf(v0.y - m);
    v0.z = expf(v0.z - m); v0.w = expf(v0.w - m);
    v1.x = expf(v1.x - m); v1.y = expf(v1.y - m);
    v1.z = expf(v1.z - m); v1.w = expf(v1.w - m);

    float s8 = v0.x + v0.y + v0.z + v0.w + v1.x + v1.y + v1.z + v1.w;
    red[tid] = s8; __syncthreads();
    for (int s = 64; s > 0; s >>= 1) {
        if (tid < s) red[tid] += red[tid + s];
        __syncthreads();
    }
    float inv = 1.0f / red[0];

    v0.x *= inv; v0.y *= inv; v0.z *= inv; v0.w *= inv;
    v1.x *= inv; v1.y *= inv; v1.z *= inv; v1.w *= inv;
    *(float4*)(p + tid * 4)       = v0;
    *(float4*)(p + 512 + tid * 4) = v1;
}

// =================================================================
// K4: ctx = P @ V per (b,h): 1024x64, K=1024. V transposed on the fly.
// 8 warps: 4m x 2n, warp tile 32x32. Bs stride 17 (conflict-free STS).
// =================================================================
__global__ void __launch_bounds__(256) ctx_kernel()
{
    __shared__ float As[2][128 * 20];
    __shared__ float Bs[2][64 * 17];
    const int bz = blockIdx.z;              // b*NH + h
    const int bm = blockIdx.y * 128;
    const int tid = threadIdx.x, wid = tid >> 5, lane = tid & 31;
    const int gid = lane >> 2, tig = lane & 3;
    const int warp_m = wid & 3, warp_n = wid >> 2;

    const float* P = g_scores + (size_t)bz * S_ * S_ + (size_t)bm * S_;
    const float* V = g_v + (size_t)bz * S_ * HD_;

    float acc[2][4][4];
#pragma unroll
    for (int i = 0; i < 2; i++)
#pragma unroll
        for (int j = 0; j < 4; j++)
#pragma unroll
            for (int k = 0; k < 4; k++) acc[i][j][k] = 0.f;

    const int kb = tid >> 6;    // 0..3
    const int dd = tid & 63;    // 0..63
    float vr[4];

    // prologue: chunk 0
    cpa_tile128x16(As[0], P, S_);
    cp_commit();
#pragma unroll
    for (int it = 0; it < 4; it++)
        vr[it] = V[(size_t)(kb + it * 4) * HD_ + dd];
    cp_wait<0>();
    __syncthreads();
#pragma unroll
    for (int it = 0; it < 4; it++)
        Bs[0][dd * 17 + kb + it * 4] = vr[it];
    __syncthreads();

    const int NC = S_ / 16;
    for (int c = 0; c < NC; c++) {
        int cur = c & 1;
        if (c + 1 < NC) {
            cpa_tile128x16(As[cur ^ 1], P + (c + 1) * 16, S_);
            cp_commit();
#pragma unroll
            for (int it = 0; it < 4; it++)
                vr[it] = V[(size_t)((c + 1) * 16 + kb + it * 4) * HD_ + dd];
        }

        // compute chunk c
        const float* Ap = As[cur];
        const float* Bp = Bs[cur];
#pragma unroll
        for (int ks = 0; ks < 16; ks += 8) {
            uint32_t a[2][4], b[4][2];
#pragma unroll
            for (int i = 0; i < 2; i++) {
                int r = warp_m * 32 + i * 16 + gid;
                a[i][0] = __float_as_uint(Ap[r * 20 + ks + tig]);
                a[i][1] = __float_as_uint(Ap[(r + 8) * 20 + ks + tig]);
                a[i][2] = __float_as_uint(Ap[r * 20 + ks + tig + 4]);
                a[i][3] = __float_as_uint(Ap[(r + 8) * 20 + ks + tig + 4]);
            }
#pragma unroll
            for (int j = 0; j < 4; j++) {
                int n = warp_n * 32 + j * 8 + gid;
                b[j][0] = __float_as_uint(Bp[n * 17 + ks + tig]);
                b[j][1] = __float_as_uint(Bp[n * 17 + ks + tig + 4]);
            }
#pragma unroll
            for (int i = 0; i < 2; i++)
#pragma unroll
                for (int j = 0; j < 4; j++)
                    mma_tf32(acc[i][j], a[i][0], a[i][1], a[i][2], a[i][3], b[j][0], b[j][1]);
        }

        if (c + 1 < NC) cp_wait<0>();
        __syncthreads();
        if (c + 1 < NC) {
#pragma unroll
            for (int it = 0; it < 4; it++)
                Bs[cur ^ 1][dd * 17 + kb + it * 4] = vr[it];
            __syncthreads();
        }
    }

    const int bb = bz >> 4, h = bz & 15;
#pragma unroll
    for (int i = 0; i < 2; i++) {
        int q0 = bm + warp_m * 32 + i * 16 + gid;
#pragma unroll
        for (int j = 0; j < 4; j++) {
            int d = warp_n * 32 + j * 8 + tig * 2;
            *(float2*)&g_ctx[(((size_t)bb * S_ + q0) * NH_ + h) * HD_ + d] =
                make_float2(acc[i][j][0], acc[i][j][1]);
            *(float2*)&g_ctx[(((size_t)bb * S_ + q0 + 8) * NH_ + h) * HD_ + d] =
                make_float2(acc[i][j][2], acc[i][j][3]);
        }
    }
}

// =================================================================
// K5a: out projection + bias + residual. M=8192, N=1024, K=1024
// =================================================================
__global__ void __launch_bounds__(256) outproj_kernel(
    const float* __restrict__ Wout, const float* __restrict__ b_out,
    const float* __restrict__ X)
{
    __shared__ float As[2][128 * 20];
    __shared__ float Bs[2][128 * 20];
    const int bm = blockIdx.y * 128, bn = blockIdx.x * 128;
    const int tid = threadIdx.x, wid = tid >> 5, lane = tid & 31;
    const int gid = lane >> 2, tig = lane & 3;
    const int warp_m = wid >> 2, warp_n = wid & 3;

    float acc[4][4][4];
#pragma unroll
    for (int i = 0; i < 4; i++)
#pragma unroll
        for (int j = 0; j < 4; j++)
#pragma unroll
            for (int k = 0; k < 4; k++) acc[i][j][k] = 0.f;

    const float* Abase = g_ctx + (size_t)bm * HID_;
    const float* Bbase = Wout + (size_t)bn * HID_;

    cpa_tile128x16(As[0], Abase, HID_);
    cpa_tile128x16(Bs[0], Bbase, HID_);
    cp_commit();

    const int NC = HID_ / 16;
    for (int c = 0; c < NC; c++) {
        int cur = c & 1;
        if (c + 1 < NC) {
            cpa_tile128x16(As[cur ^ 1], Abase + (c + 1) * 16, HID_);
            cpa_tile128x16(Bs[cur ^ 1], Bbase + (c + 1) * 16, HID_);
            cp_commit();
            cp_wait<1>();
        } else {
            cp_wait<0>();
        }
        __syncthreads();
        mma_block_128x128(As[cur], Bs[cur], warp_m, warp_n, gid, tig, acc);
        __syncthreads();
    }

#pragma unroll
    for (int i = 0; i < 4; i++) {
        int r0 = bm + warp_m * 64 + i * 16 + gid;
#pragma unroll
        for (int j = 0; j < 4; j++) {
            int n = bn + warp_n * 32 + j * 8 + tig * 2;
            float2 x0 = *(const float2*)&X[(size_t)r0 * HID_ + n];
            float2 x1 = *(const float2*)&X[(size_t)(r0 + 8) * HID_ + n];
            float b0 = b_out[n], b1 = b_out[n + 1];
            *(float2*)&g_h[(size_t)r0 * HID_ + n] =
                make_float2(acc[i][j][0] + b0 + x0.x, acc[i][j][1] + b1 + x0.y);
            *(float2*)&g_h[(size_t)(r0 + 8) * HID_ + n] =
                make_float2(acc[i][j][2] + b0 + x1.x, acc[i][j][3] + b1 + x1.y);
        }
    }
}

// =================================================================
// K5b: LayerNorm per row of g_h -> d_out
// =================================================================
__global__ void __launch_bounds__(256) layernorm_kernel(
    const float* __restrict__ gamma, const float* __restrict__ beta,
    float* __restrict__ out)
{
    const size_t row = blockIdx.x;
    const float* hp = g_h + row * HID_;
    const int tid = threadIdx.x;
    const int n = tid * 4;

    float4 v = *(const float4*)(hp + n);
    __shared__ float red[256];

    red[tid] = v.x + v.y + v.z + v.w;
    __syncthreads();
    for (int s = 128; s > 0; s >>= 1) {
        if (tid < s) red[tid] += red[tid + s];
        __syncthreads();
    }
    float mean = red[0] * (1.0f / HID_);
    __syncthreads();

    float dx = v.x - mean, dy = v.y - mean, dz = v.z - mean, dw = v.w - mean;
    red[tid] = dx * dx + dy * dy + dz * dz + dw * dw;
    __syncthreads();
    for (int s = 128; s > 0; s >>= 1) {
        if (tid < s) red[tid] += red[tid + s];
        __syncthreads();
    }
    float inv = rsqrtf(red[0] * (1.0f / HID_) + 1e-12f);

    float4 o;
    o.x = dx * inv * gamma[n + 0] + beta[n + 0];
    o.y = dy * inv * gamma[n + 1] + beta[n + 1];
    o.z = dz * inv * gamma[n + 2] + beta[n + 2];
    o.w = dw * inv * gamma[n + 3] + beta[n + 3];
    *(float4*)(out + row * HID_ + n) = o;
}

// =================================================================
extern "C" void kernel_launch(void* const* d_in, const int* in_sizes, int n_in,
                              void* d_out, int out_size)
{
    const float*         x       = (const float*)d_in[0];
    const unsigned char* mask    = (const unsigned char*)d_in[1];
    const float*         rel_pos = (const float*)d_in[2];
    const float*         rel2d   = (const float*)d_in[3];
    const float*         w_qkv   = (const float*)d_in[4];
    const float*         q_bias  = (const float*)d_in[5];
    const float*         v_bias  = (const float*)d_in[6];
    const float*         w_out   = (const float*)d_in[7];
    const float*         b_out   = (const float*)d_in[8];
    const float*         gamma   = (const float*)d_in[9];
    const float*         beta    = (const float*)d_in[10];
    float*               out     = (float*)d_out;

    qkv_gemm_kernel<<<dim3(24, 64), 256>>>(x, w_qkv, q_bias, v_bias);
    scores_kernel<<<dim3(8, 8, B_ * NH_), 256>>>(rel_pos, rel2d, mask);
    softmax_kernel<<<dim3(B_ * NH_ * S_), 128>>>();
    ctx_kernel<<<dim3(1, 8, B_ * NH_), 256>>>();
    outproj_kernel<<<dim3(8, 64), 256>>>(w_out, b_out, x);
    layernorm_kernel<<<dim3(B_ * S_), 256>>>(gamma, beta, out);
}

// round 4
// speedup vs baseline: 3.3670x; 1.2095x over previous
#include <cuda_runtime.h>
#include <cstdint>

#define B_   8
#define S_   1024
#define HID_ 1024
#define NH_  16
#define HD_  64

// ---------------- scratch (no allocations allowed) ----------------
__device__ float g_q[B_ * NH_ * S_ * HD_];   // [b,h,s,d], pre-scaled 1/8, +q_bias
__device__ float g_k[B_ * NH_ * S_ * HD_];
__device__ float g_v[B_ * NH_ * S_ * HD_];
__device__ float g_ctx[B_ * S_ * HID_];      // [b,s,h,d]
__device__ float g_h[B_ * S_ * HID_];

// ---------------- helpers ----------------
__device__ __forceinline__ uint32_t smem_u32(const void* p) {
    return (uint32_t)__cvta_generic_to_shared(p);
}
__device__ __forceinline__ void cp16(uint32_t s, const void* g) {
    asm volatile("cp.async.cg.shared.global [%0], [%1], 16;\n" :: "r"(s), "l"(g));
}
__device__ __forceinline__ void cp_commit() { asm volatile("cp.async.commit_group;\n"); }
template<int N> __device__ __forceinline__ void cp_wait() {
    asm volatile("cp.async.wait_group %0;\n" :: "n"(N));
}
__device__ __forceinline__ void mma_tf32(float c[4],
    uint32_t a0, uint32_t a1, uint32_t a2, uint32_t a3, uint32_t b0, uint32_t b1)
{
    asm volatile(
        "mma.sync.aligned.m16n8k8.row.col.f32.tf32.tf32.f32 "
        "{%0,%1,%2,%3},{%4,%5,%6,%7},{%8,%9},{%0,%1,%2,%3};\n"
        : "+f"(c[0]), "+f"(c[1]), "+f"(c[2]), "+f"(c[3])
        : "r"(a0), "r"(a1), "r"(a2), "r"(a3), "r"(b0), "r"(b1));
}

// load 128 rows x 16 floats tile into smem [row*20 + col] via cp.async
__device__ __forceinline__ void cpa_tile128x16(float* dst, const float* src, int ld) {
    const int tid = threadIdx.x;
    const int row = tid >> 2;
    const int c4  = (tid & 3) * 4;
    cp16(smem_u32(dst + row * 20 + c4),        src + (size_t)row * ld + c4);
    cp16(smem_u32(dst + (row + 64) * 20 + c4), src + (size_t)(row + 64) * ld + c4);
}

// load 128 rows x 64 floats into smem [row*68 + col] via cp.async (8 cp16/thread)
__device__ __forceinline__ void cpa_tile128x64(float* dst, const float* src) {
    const int tid = threadIdx.x;
#pragma unroll
    for (int i = 0; i < 8; i++) {
        int idx = tid + i * 256;
        int r = idx >> 4, c = (idx & 15) * 4;
        cp16(smem_u32(dst + r * 68 + c), src + (size_t)r * HD_ + c);
    }
}

// 128x128 block-tile compute on one BK=16 chunk (8 warps: 2m x 4n, warp tile 64x32)
__device__ __forceinline__ void mma_block_128x128(
    const float* As, const float* Bs,
    int warp_m, int warp_n, int gid, int tig, float acc[4][4][4])
{
#pragma unroll
    for (int ks = 0; ks < 16; ks += 8) {
        uint32_t a[4][4], b[4][2];
#pragma unroll
        for (int i = 0; i < 4; i++) {
            int r = warp_m * 64 + i * 16 + gid;
            a[i][0] = __float_as_uint(As[r * 20 + ks + tig]);
            a[i][1] = __float_as_uint(As[(r + 8) * 20 + ks + tig]);
            a[i][2] = __float_as_uint(As[r * 20 + ks + tig + 4]);
            a[i][3] = __float_as_uint(As[(r + 8) * 20 + ks + tig + 4]);
        }
#pragma unroll
        for (int j = 0; j < 4; j++) {
            int n = warp_n * 32 + j * 8 + gid;
            b[j][0] = __float_as_uint(Bs[n * 20 + ks + tig]);
            b[j][1] = __float_as_uint(Bs[n * 20 + ks + tig + 4]);
        }
#pragma unroll
        for (int i = 0; i < 4; i++)
#pragma unroll
            for (int j = 0; j < 4; j++)
                mma_tf32(acc[i][j], a[i][0], a[i][1], a[i][2], a[i][3], b[j][0], b[j][1]);
    }
}

// =================================================================
// K1: QKV projection. C[m,n] = X[m,:] . W[n,:], M=8192, N=3072, K=1024
// =================================================================
__device__ __forceinline__ void qkv_store(int bb, int ss, int n, float2 v,
                                          const float* qb, const float* vb)
{
    if (n < HID_) {
        float2 o;
        o.x = (v.x + qb[n]) * 0.125f;
        o.y = (v.y + qb[n + 1]) * 0.125f;
        int h = n >> 6, d = n & 63;
        *(float2*)&g_q[(((size_t)(bb * NH_ + h)) * S_ + ss) * HD_ + d] = o;
    } else if (n < 2 * HID_) {
        int nn = n - HID_;
        int h = nn >> 6, d = nn & 63;
        *(float2*)&g_k[(((size_t)(bb * NH_ + h)) * S_ + ss) * HD_ + d] = v;
    } else {
        int nn = n - 2 * HID_;
        float2 o;
        o.x = v.x + vb[nn];
        o.y = v.y + vb[nn + 1];
        int h = nn >> 6, d = nn & 63;
        *(float2*)&g_v[(((size_t)(bb * NH_ + h)) * S_ + ss) * HD_ + d] = o;
    }
}

__global__ void __launch_bounds__(256) qkv_gemm_kernel(
    const float* __restrict__ X, const float* __restrict__ W,
    const float* __restrict__ qb, const float* __restrict__ vb)
{
    __shared__ float As[2][128 * 20];
    __shared__ float Bs[2][128 * 20];
    const int bm = blockIdx.y * 128, bn = blockIdx.x * 128;
    const int tid = threadIdx.x, wid = tid >> 5, lane = tid & 31;
    const int gid = lane >> 2, tig = lane & 3;
    const int warp_m = wid >> 2, warp_n = wid & 3;

    float acc[4][4][4];
#pragma unroll
    for (int i = 0; i < 4; i++)
#pragma unroll
        for (int j = 0; j < 4; j++)
#pragma unroll
            for (int k = 0; k < 4; k++) acc[i][j][k] = 0.f;

    const float* Abase = X + (size_t)bm * HID_;
    const float* Bbase = W + (size_t)bn * HID_;

    cpa_tile128x16(As[0], Abase, HID_);
    cpa_tile128x16(Bs[0], Bbase, HID_);
    cp_commit();

    const int NC = HID_ / 16;
    for (int c = 0; c < NC; c++) {
        int cur = c & 1;
        if (c + 1 < NC) {
            cpa_tile128x16(As[cur ^ 1], Abase + (c + 1) * 16, HID_);
            cpa_tile128x16(Bs[cur ^ 1], Bbase + (c + 1) * 16, HID_);
            cp_commit();
            cp_wait<1>();
        } else {
            cp_wait<0>();
        }
        __syncthreads();
        mma_block_128x128(As[cur], Bs[cur], warp_m, warp_n, gid, tig, acc);
        __syncthreads();
    }

    const int bb = bm >> 10, ss0 = bm & 1023;
#pragma unroll
    for (int i = 0; i < 4; i++) {
        int r = warp_m * 64 + i * 16 + gid;
#pragma unroll
        for (int j = 0; j < 4; j++) {
            int n = bn + warp_n * 32 + j * 8 + tig * 2;
            qkv_store(bb, ss0 + r,     n, make_float2(acc[i][j][0], acc[i][j][1]), qb, vb);
            qkv_store(bb, ss0 + r + 8, n, make_float2(acc[i][j][2], acc[i][j][3]), qb, vb);
        }
    }
}

// =================================================================
// K2 (FUSED): flash attention with rel-pos biases.
// CTA = (b = blockIdx.x, qt = blockIdx.y, h = blockIdx.z), 128 q-rows.
// Loops over 8 K/V tiles of 128; online softmax; ctx accumulated in regs.
// =================================================================
#define VS_STRIDE 132
#define FUSED_SMEM (128*68*4 /*Qs*/ + 2*128*68*4 /*Ks*/ + 64*VS_STRIDE*4 /*Vs*/ + 512 /*mask*/)

extern __shared__ float dynsmem[];

__global__ void __launch_bounds__(256, 1) fused_attn_kernel(
    const float* __restrict__ rel_pos, const float* __restrict__ rel2d,
    const unsigned char* __restrict__ mask)
{
    const int b  = blockIdx.x;
    const int qt = blockIdx.y;
    const int h  = blockIdx.z;
    const int bh = b * NH_ + h;

    float* Qs = dynsmem;                       // [128][68]
    float* Ks = Qs + 128 * 68;                 // 2 x [128][68]
    float* Vs = Ks + 2 * 128 * 68;             // [64][VS_STRIDE]
    float* smaskf = Vs + 64 * VS_STRIDE;       // [128]

    const int tid = threadIdx.x, wid = tid >> 5, lane = tid & 31;
    const int gid = lane >> 2, tig = lane & 3;
    const int kb = tid >> 6;                   // 0..3 (V load)
    const int dd = tid & 63;                   // 0..63 (V load)

    const float* Qg = g_q + (size_t)bh * S_ * HD_ + (size_t)(qt * 128) * HD_;
    const float* Kg = g_k + (size_t)bh * S_ * HD_;
    const float* Vg = g_v + (size_t)bh * S_ * HD_;

    // prologue: Q tile, first K tile
    cpa_tile128x64(Qs, Qg);
    cp_commit();
    cpa_tile128x64(Ks, Kg);
    cp_commit();
    cp_wait<1>();       // Qs ready
    __syncthreads();

    // preload Q fragments (warp owns rows wid*16 .. wid*16+15)
    const int r0 = wid * 16 + gid;
    uint32_t qa[8][4];
#pragma unroll
    for (int kk = 0; kk < 8; kk++) {
        qa[kk][0] = __float_as_uint(Qs[r0 * 68 + kk * 8 + tig]);
        qa[kk][1] = __float_as_uint(Qs[(r0 + 8) * 68 + kk * 8 + tig]);
        qa[kk][2] = __float_as_uint(Qs[r0 * 68 + kk * 8 + tig + 4]);
        qa[kk][3] = __float_as_uint(Qs[(r0 + 8) * 68 + kk * 8 + tig + 4]);
    }

    // online softmax state (rows ra = qt*128+r0, rb = ra+8)
    float m_a = -1e30f, m_b = -1e30f;
    float l_a = 0.f,    l_b = 0.f;
    float cacc[8][4];
#pragma unroll
    for (int jj = 0; jj < 8; jj++)
#pragma unroll
        for (int k = 0; k < 4; k++) cacc[jj][k] = 0.f;

    const int ra = qt * 128 + r0;
    const float* rpA = rel_pos + ((size_t)h * S_ + ra) * S_;
    const float* rpB = rel_pos + ((size_t)h * S_ + ra + 8) * S_;
    const float* r2A = rel2d   + ((size_t)h * S_ + ra) * S_;
    const float* r2B = rel2d   + ((size_t)h * S_ + ra + 8) * S_;
    const unsigned char* mrow = mask + b * S_;

    for (int kt = 0; kt < 8; kt++) {
        const int cur = kt & 1;
        if (kt + 1 < 8) {
            cpa_tile128x64(Ks + (cur ^ 1) * 128 * 68, Kg + (size_t)(kt + 1) * 128 * HD_);
            cp_commit();
        }
        // V wave 1 LDG (overlaps S-MMA)
        float vr[16];
#pragma unroll
        for (int it = 0; it < 16; it++)
            vr[it] = Vg[(size_t)(kt * 128 + it * 4 + kb) * HD_ + dd];
        // mask tile to smem
        if (tid < 128) smaskf[tid] = mrow[kt * 128 + tid] ? -1e30f : 0.f;

        if (kt + 1 < 8) cp_wait<1>(); else cp_wait<0>();
        __syncthreads();   // Ks[cur] ready; prev iter fully done (Vs reusable)

        // ---- S-tile = Q . K^T : warp computes 16 x 128, 16 j-tiles ----
        const float* Kp = Ks + cur * 128 * 68;
        float s[16][4];
#pragma unroll
        for (int j = 0; j < 16; j++)
#pragma unroll
            for (int k = 0; k < 4; k++) s[j][k] = 0.f;
#pragma unroll
        for (int kk = 0; kk < 8; kk++) {
#pragma unroll
            for (int j = 0; j < 16; j++) {
                int n = j * 8 + gid;
                uint32_t b0 = __float_as_uint(Kp[n * 68 + kk * 8 + tig]);
                uint32_t b1 = __float_as_uint(Kp[n * 68 + kk * 8 + tig + 4]);
                mma_tf32(s[j], qa[kk][0], qa[kk][1], qa[kk][2], qa[kk][3], b0, b1);
            }
        }

        // ---- epilogue: + rel_pos + rel_2d + mask; track tile row max ----
        float mxa = -1e30f, mxb = -1e30f;
        const size_t coff = (size_t)kt * 128;
#pragma unroll
        for (int jg = 0; jg < 4; jg++) {
            float2 pa[4], qa2[4], pb[4], qb2[4];
#pragma unroll
            for (int jj = 0; jj < 4; jj++) {
                int n = (jg * 4 + jj) * 8 + tig * 2;
                pa[jj]  = *(const float2*)&rpA[coff + n];
                qa2[jj] = *(const float2*)&r2A[coff + n];
                pb[jj]  = *(const float2*)&rpB[coff + n];
                qb2[jj] = *(const float2*)&r2B[coff + n];
            }
#pragma unroll
            for (int jj = 0; jj < 4; jj++) {
                int j = jg * 4 + jj;
                int n = j * 8 + tig * 2;
                float m0 = smaskf[n], m1 = smaskf[n + 1];
                s[j][0] += pa[jj].x + qa2[jj].x + m0;
                s[j][1] += pa[jj].y + qa2[jj].y + m1;
                s[j][2] += pb[jj].x + qb2[jj].x + m0;
                s[j][3] += pb[jj].y + qb2[jj].y + m1;
                mxa = fmaxf(mxa, fmaxf(s[j][0], s[j][1]));
                mxb = fmaxf(mxb, fmaxf(s[j][2], s[j][3]));
            }
        }
        // reduce max over the 4 lanes holding this row
        mxa = fmaxf(mxa, __shfl_xor_sync(0xffffffffu, mxa, 1));
        mxa = fmaxf(mxa, __shfl_xor_sync(0xffffffffu, mxa, 2));
        mxb = fmaxf(mxb, __shfl_xor_sync(0xffffffffu, mxb, 1));
        mxb = fmaxf(mxb, __shfl_xor_sync(0xffffffffu, mxb, 2));

        float mna = fmaxf(m_a, mxa), mnb = fmaxf(m_b, mxb);
        float sca = __expf(m_a - mna), scb = __expf(m_b - mnb);
        m_a = mna; m_b = mnb;

        float suma = 0.f, sumb = 0.f;
#pragma unroll
        for (int j = 0; j < 16; j++) {
            s[j][0] = __expf(s[j][0] - m_a);
            s[j][1] = __expf(s[j][1] - m_a);
            s[j][2] = __expf(s[j][2] - m_b);
            s[j][3] = __expf(s[j][3] - m_b);
            suma += s[j][0] + s[j][1];
            sumb += s[j][2] + s[j][3];
        }
        l_a = l_a * sca + suma;
        l_b = l_b * scb + sumb;
#pragma unroll
        for (int jj = 0; jj < 8; jj++) {
            cacc[jj][0] *= sca; cacc[jj][1] *= sca;
            cacc[jj][2] *= scb; cacc[jj][3] *= scb;
        }

        // ---- V transpose to smem: Vs[d][k] ----
#pragma unroll
        for (int it = 0; it < 16; it++)
            Vs[dd * VS_STRIDE + it * 4 + kb] = vr[it];
#pragma unroll
        for (int it = 0; it < 16; it++)
            vr[it] = Vg[(size_t)(kt * 128 + (it + 16) * 4 + kb) * HD_ + dd];
#pragma unroll
        for (int it = 0; it < 16; it++)
            Vs[dd * VS_STRIDE + (it + 16) * 4 + kb] = vr[it];
        __syncthreads();   // Vs ready

        // ---- ctx += P . V : 16 k-chunks, P frags from s[] via shuffles ----
        const int base = lane & ~3;
        const int src_lo = base + (tig >> 1);
        const int src_hi = src_lo + 2;
        const bool odd = (tig & 1);
#pragma unroll
        for (int j = 0; j < 16; j++) {
            float t0 = __shfl_sync(0xffffffffu, s[j][0], src_lo);
            float t1 = __shfl_sync(0xffffffffu, s[j][1], src_lo);
            float u0 = __shfl_sync(0xffffffffu, s[j][0], src_hi);
            float u1 = __shfl_sync(0xffffffffu, s[j][1], src_hi);
            float v0 = __shfl_sync(0xffffffffu, s[j][2], src_lo);
            float v1 = __shfl_sync(0xffffffffu, s[j][3], src_lo);
            float w0 = __shfl_sync(0xffffffffu, s[j][2], src_hi);
            float w1 = __shfl_sync(0xffffffffu, s[j][3], src_hi);
            uint32_t a0 = __float_as_uint(odd ? t1 : t0);
            uint32_t a2 = __float_as_uint(odd ? u1 : u0);
            uint32_t a1 = __float_as_uint(odd ? v1 : v0);
            uint32_t a3 = __float_as_uint(odd ? w1 : w0);
#pragma unroll
            for (int jj = 0; jj < 8; jj++) {
                int d = jj * 8 + gid;
                uint32_t b0 = __float_as_uint(Vs[d * VS_STRIDE + j * 8 + tig]);
                uint32_t b1 = __float_as_uint(Vs[d * VS_STRIDE + j * 8 + tig + 4]);
                mma_tf32(cacc[jj], a0, a1, a2, a3, b0, b1);
            }
        }
    }

    // final: reduce l across 4 lanes, normalize, write ctx [b,s,h,d]
    l_a += __shfl_xor_sync(0xffffffffu, l_a, 1);
    l_a += __shfl_xor_sync(0xffffffffu, l_a, 2);
    l_b += __shfl_xor_sync(0xffffffffu, l_b, 1);
    l_b += __shfl_xor_sync(0xffffffffu, l_b, 2);
    float inva = 1.0f / l_a, invb = 1.0f / l_b;

    const size_t obase_a = (((size_t)b * S_ + ra) * NH_ + h) * HD_;
    const size_t obase_b = (((size_t)b * S_ + ra + 8) * NH_ + h) * HD_;
#pragma unroll
    for (int jj = 0; jj < 8; jj++) {
        int d = jj * 8 + tig * 2;
        *(float2*)&g_ctx[obase_a + d] =
            make_float2(cacc[jj][0] * inva, cacc[jj][1] * inva);
        *(float2*)&g_ctx[obase_b + d] =
            make_float2(cacc[jj][2] * invb, cacc[jj][3] * invb);
    }
}

// =================================================================
// K3: out projection + bias + residual. M=8192, N=1024, K=1024
// =================================================================
__global__ void __launch_bounds__(256) outproj_kernel(
    const float* __restrict__ Wout, const float* __restrict__ b_out,
    const float* __restrict__ X)
{
    __shared__ float As[2][128 * 20];
    __shared__ float Bs[2][128 * 20];
    const int bm = blockIdx.y * 128, bn = blockIdx.x * 128;
    const int tid = threadIdx.x, wid = tid >> 5, lane = tid & 31;
    const int gid = lane >> 2, tig = lane & 3;
    const int warp_m = wid >> 2, warp_n = wid & 3;

    float acc[4][4][4];
#pragma unroll
    for (int i = 0; i < 4; i++)
#pragma unroll
        for (int j = 0; j < 4; j++)
#pragma unroll
            for (int k = 0; k < 4; k++) acc[i][j][k] = 0.f;

    const float* Abase = g_ctx + (size_t)bm * HID_;
    const float* Bbase = Wout + (size_t)bn * HID_;

    cpa_tile128x16(As[0], Abase, HID_);
    cpa_tile128x16(Bs[0], Bbase, HID_);
    cp_commit();

    const int NC = HID_ / 16;
    for (int c = 0; c < NC; c++) {
        int cur = c & 1;
        if (c + 1 < NC) {
            cpa_tile128x16(As[cur ^ 1], Abase + (c + 1) * 16, HID_);
            cpa_tile128x16(Bs[cur ^ 1], Bbase + (c + 1) * 16, HID_);
            cp_commit();
            cp_wait<1>();
        } else {
            cp_wait<0>();
        }
        __syncthreads();
        mma_block_128x128(As[cur], Bs[cur], warp_m, warp_n, gid, tig, acc);
        __syncthreads();
    }

#pragma unroll
    for (int i = 0; i < 4; i++) {
        int r0 = bm + warp_m * 64 + i * 16 + gid;
#pragma unroll
        for (int j = 0; j < 4; j++) {
            int n = bn + warp_n * 32 + j * 8 + tig * 2;
            float2 x0 = *(const float2*)&X[(size_t)r0 * HID_ + n];
            float2 x1 = *(const float2*)&X[(size_t)(r0 + 8) * HID_ + n];
            float b0 = b_out[n], b1 = b_out[n + 1];
            *(float2*)&g_h[(size_t)r0 * HID_ + n] =
                make_float2(acc[i][j][0] + b0 + x0.x, acc[i][j][1] + b1 + x0.y);
            *(float2*)&g_h[(size_t)(r0 + 8) * HID_ + n] =
                make_float2(acc[i][j][2] + b0 + x1.x, acc[i][j][3] + b1 + x1.y);
        }
    }
}

// =================================================================
// K4: LayerNorm per row of g_h -> d_out
// =================================================================
__global__ void __launch_bounds__(256) layernorm_kernel(
    const float* __restrict__ gamma, const float* __restrict__ beta,
    float* __restrict__ out)
{
    const size_t row = blockIdx.x;
    const float* hp = g_h + row * HID_;
    const int tid = threadIdx.x;
    const int n = tid * 4;

    float4 v = *(const float4*)(hp + n);
    __shared__ float red[256];

    red[tid] = v.x + v.y + v.z + v.w;
    __syncthreads();
    for (int s = 128; s > 0; s >>= 1) {
        if (tid < s) red[tid] += red[tid + s];
        __syncthreads();
    }
    float mean = red[0] * (1.0f / HID_);
    __syncthreads();

    float dx = v.x - mean, dy = v.y - mean, dz = v.z - mean, dw = v.w - mean;
    red[tid] = dx * dx + dy * dy + dz * dz + dw * dw;
    __syncthreads();
    for (int s = 128; s > 0; s >>= 1) {
        if (tid < s) red[tid] += red[tid + s];
        __syncthreads();
    }
    float inv = rsqrtf(red[0] * (1.0f / HID_) + 1e-12f);

    float4 o;
    o.x = dx * inv * gamma[n + 0] + beta[n + 0];
    o.y = dy * inv * gamma[n + 1] + beta[n + 1];
    o.z = dz * inv * gamma[n + 2] + beta[n + 2];
    o.w = dw * inv * gamma[n + 3] + beta[n + 3];
    *(float4*)(out + row * HID_ + n) = o;
}

// =================================================================
extern "C" void kernel_launch(void* const* d_in, const int* in_sizes, int n_in,
                              void* d_out, int out_size)
{
    const float*         x       = (const float*)d_in[0];
    const unsigned char* mask    = (const unsigned char*)d_in[1];
    const float*         rel_pos = (const float*)d_in[2];
    const float*         rel2d   = (const float*)d_in[3];
    const float*         w_qkv   = (const float*)d_in[4];
    const float*         q_bias  = (const float*)d_in[5];
    const float*         v_bias  = (const float*)d_in[6];
    const float*         w_out   = (const float*)d_in[7];
    const float*         b_out   = (const float*)d_in[8];
    const float*         gamma   = (const float*)d_in[9];
    const float*         beta    = (const float*)d_in[10];
    float*               out     = (float*)d_out;

    static bool attr_set = false;
    // setting the same attribute every call is deterministic & idempotent
    cudaFuncSetAttribute(fused_attn_kernel,
                         cudaFuncAttributeMaxDynamicSharedMemorySize, FUSED_SMEM);
    (void)attr_set;

    qkv_gemm_kernel<<<dim3(24, 64), 256>>>(x, w_qkv, q_bias, v_bias);
    fused_attn_kernel<<<dim3(B_, 8, NH_), 256, FUSED_SMEM>>>(rel_pos, rel2d, mask);
    outproj_kernel<<<dim3(8, 64), 256>>>(w_out, b_out, x);
    layernorm_kernel<<<dim3(B_ * S_), 256>>>(gamma, beta, out);
}